// round 2
// baseline (speedup 1.0000x reference)
#include <cuda_runtime.h>
#include <cuda_bf16.h>
#include <stdint.h>

#define NB     16384
#define PD     128
#define PITCH  136     // bf16 elements per smem row (128 + 8 pad; 272B = 17*16B, ldmatrix conflict-free)
#define PITCHF 132     // float pitch for normalization buffer
#define SMEM_BYTES (2*128*PITCH*2)   // 69632 B: two 128x136 bf16 tiles

// ---------------- device scratch (allocation-free) ----------------
__device__ __nv_bfloat16 g_Wi1[2048*PD];
__device__ __nv_bfloat16 g_Wi2[PD*PD];
__device__ __nv_bfloat16 g_Wn1[256*PD];
__device__ __nv_bfloat16 g_Wn2[PD*PD];
__device__ __nv_bfloat16 g_ip[NB*PD];   // normalized img embeddings (bf16)
__device__ __nv_bfloat16 g_np[NB*PD];   // normalized num embeddings * log2(e)/temp
__device__ float g_rowsum[NB];
__device__ float g_colsum[NB];
__device__ float g_part[64];

// ---------------- asm helpers ----------------
static __device__ __forceinline__ uint32_t smem_u32(const void* p){
    return (uint32_t)__cvta_generic_to_shared(p);
}
static __device__ __forceinline__ void ldsm_x4(uint32_t r[4], uint32_t a){
    asm volatile("ldmatrix.sync.aligned.m8n8.x4.shared.b16 {%0,%1,%2,%3},[%4];"
        : "=r"(r[0]),"=r"(r[1]),"=r"(r[2]),"=r"(r[3]) : "r"(a));
}
static __device__ __forceinline__ void ldsm_x2(uint32_t r[2], uint32_t a){
    asm volatile("ldmatrix.sync.aligned.m8n8.x2.shared.b16 {%0,%1},[%2];"
        : "=r"(r[0]),"=r"(r[1]) : "r"(a));
}
static __device__ __forceinline__ void ldsm_x2t(uint32_t r[2], uint32_t a){
    asm volatile("ldmatrix.sync.aligned.m8n8.x2.trans.shared.b16 {%0,%1},[%2];"
        : "=r"(r[0]),"=r"(r[1]) : "r"(a));
}
static __device__ __forceinline__ void mma16816(float c[4], const uint32_t a[4], const uint32_t b[2]){
    asm("mma.sync.aligned.m16n8k16.row.col.f32.bf16.bf16.f32 "
        "{%0,%1,%2,%3},{%4,%5,%6,%7},{%8,%9},{%0,%1,%2,%3};"
        : "+f"(c[0]),"+f"(c[1]),"+f"(c[2]),"+f"(c[3])
        : "r"(a[0]),"r"(a[1]),"r"(a[2]),"r"(a[3]),"r"(b[0]),"r"(b[1]));
}
static __device__ __forceinline__ float ex2f(float x){
    float r; asm("ex2.approx.f32 %0,%1;" : "=f"(r) : "f"(x)); return r;
}

// A fragment: smem row-major [m][PITCH] bf16, 16x16 tile at (m0,k0)
static __device__ __forceinline__ void lda(uint32_t a[4], uint32_t base, int m0, int k0, int lane){
    int row = m0 + (lane & 7) + ((lane >> 3) & 1) * 8;
    int kk  = k0 + ((lane >> 4) << 3);
    ldsm_x4(a, base + (uint32_t)(row*PITCH + kk)*2u);
}
// B fragment from [n][k] row-major storage (non-trans), 16(k)x8(n) at (n0,k0)
static __device__ __forceinline__ void ldb_nk(uint32_t b[2], uint32_t base, int n0, int k0, int lane){
    int l = lane & 15;
    int row = n0 + (l & 7);
    int kk  = k0 + ((l >> 3) << 3);
    ldsm_x2(b, base + (uint32_t)(row*PITCH + kk)*2u);
}
// B fragment from [k][n] row-major storage (trans), 16(k)x8(n) at (n0,k0)
static __device__ __forceinline__ void ldb_kn(uint32_t b[2], uint32_t base, int n0, int k0, int lane){
    int row = k0 + (lane & 15);
    ldsm_x2t(b, base + (uint32_t)(row*PITCH + n0)*2u);
}

// ---------------- prep kernels ----------------
__global__ void convert_weights(const float* __restrict__ Wi1, const float* __restrict__ Wi2,
                                const float* __restrict__ Wn1, const float* __restrict__ Wn2)
{
    int i = blockIdx.x*blockDim.x + threadIdx.x;   // 262144 threads
    if (i < 2048*PD) g_Wi1[i] = __float2bfloat16(Wi1[i]);
    if (i < PD*PD)  { g_Wi2[i] = __float2bfloat16(Wi2[i]);
                      g_Wn2[i] = __float2bfloat16(Wn2[i]); }
    if (i < 256*PD)  g_Wn1[i] = __float2bfloat16(Wn1[i]);
}

__global__ void zero_sums(){
    int i = blockIdx.x*blockDim.x + threadIdx.x;   // 32768 threads
    if (i < NB) g_rowsum[i] = 0.f; else g_colsum[i-NB] = 0.f;
}

// ---------------- fused 2-layer MLP + ReLU + L2-norm ----------------
// 128 rows/CTA, 256 threads, warps 4(m)x2(n), warp tile 32x64.
template<int D>
__global__ __launch_bounds__(256)
void mlp_norm(const float* __restrict__ X,
              const float* __restrict__ b1g,
              const float* __restrict__ b2g,
              const float* __restrict__ lt,
              int which)                  // 0 = img -> g_ip, 1 = num -> g_np (scaled)
{
    extern __shared__ __nv_bfloat16 sm[];
    __nv_bfloat16* SA = sm;
    __nv_bfloat16* SB = sm + 128*PITCH;
    const __nv_bfloat16* W1 = which ? g_Wn1 : g_Wi1;
    const __nv_bfloat16* W2 = which ? g_Wn2 : g_Wi2;
    __nv_bfloat16*       E  = which ? g_np  : g_ip;

    const int tid = threadIdx.x, lane = tid & 31, warp = tid >> 5;
    const int wm = warp & 3, wn = warp >> 2;
    const int rowbase = blockIdx.x * 128;
    const uint32_t sa = smem_u32(SA), sb = smem_u32(SB);

    // ---- layer 1: h = relu(X @ W1 + b1) ----
    float acc1[2][8][4];
    #pragma unroll
    for (int i=0;i<2;i++)
        #pragma unroll
        for (int j=0;j<8;j++)
            #pragma unroll
            for (int k=0;k<4;k++) acc1[i][j][k] = 0.f;

    for (int kc = 0; kc < D/64; kc++){
        __syncthreads();
        #pragma unroll
        for (int it=0; it<8; it++){                  // X chunk 128x64 fp32 -> bf16
            int idx = it*256 + tid;
            int r = idx >> 4, c4 = idx & 15;
            float4 v = *(const float4*)(X + (size_t)(rowbase+r)*D + kc*64 + c4*4);
            __nv_bfloat162* dst = (__nv_bfloat162*)(SA + r*PITCH + c4*4);
            dst[0] = __floats2bfloat162_rn(v.x, v.y);
            dst[1] = __floats2bfloat162_rn(v.z, v.w);
        }
        #pragma unroll
        for (int it=0; it<4; it++){                  // W1 chunk 64x128 bf16 ([k][n])
            int idx = it*256 + tid;
            int r = idx >> 4, c8 = (idx & 15)*8;
            *(uint4*)(SB + r*PITCH + c8) = *(const uint4*)(W1 + (size_t)(kc*64+r)*PD + c8);
        }
        __syncthreads();
        #pragma unroll
        for (int ks=0; ks<4; ks++){
            int k0 = ks*16;
            uint32_t a[2][4], b[2];
            lda(a[0], sa, wm*32,    k0, lane);
            lda(a[1], sa, wm*32+16, k0, lane);
            #pragma unroll
            for (int ni=0; ni<8; ni++){
                ldb_kn(b, sb, wn*64+ni*8, k0, lane);
                mma16816(acc1[0][ni], a[0], b);
                mma16816(acc1[1][ni], a[1], b);
            }
        }
    }
    __syncthreads();

    // bias + relu -> SA as bf16 [m][PITCH]; stage W2 -> SB
    #pragma unroll
    for (int mi=0; mi<2; mi++)
        #pragma unroll
        for (int ni=0; ni<8; ni++){
            int r0 = wm*32 + mi*16 + (lane>>2);
            int c  = wn*64 + ni*8 + 2*(lane&3);
            float ba = b1g[c], bb = b1g[c+1];
            *(__nv_bfloat162*)(SA + r0*PITCH + c) =
                __floats2bfloat162_rn(fmaxf(acc1[mi][ni][0]+ba,0.f), fmaxf(acc1[mi][ni][1]+bb,0.f));
            *(__nv_bfloat162*)(SA + (r0+8)*PITCH + c) =
                __floats2bfloat162_rn(fmaxf(acc1[mi][ni][2]+ba,0.f), fmaxf(acc1[mi][ni][3]+bb,0.f));
        }
    #pragma unroll
    for (int it=0; it<8; it++){                      // W2 128x128 bf16 ([k][n])
        int idx = it*256 + tid;
        int r = idx >> 4, c8 = (idx & 15)*8;
        *(uint4*)(SB + r*PITCH + c8) = *(const uint4*)(W2 + (size_t)r*PD + c8);
    }
    __syncthreads();

    // ---- layer 2: e = h @ W2 + b2 ----
    float acc2[2][8][4];
    #pragma unroll
    for (int i=0;i<2;i++)
        #pragma unroll
        for (int j=0;j<8;j++)
            #pragma unroll
            for (int k=0;k<4;k++) acc2[i][j][k] = 0.f;

    #pragma unroll
    for (int ks=0; ks<8; ks++){
        int k0 = ks*16;
        uint32_t a[2][4], b[2];
        lda(a[0], sa, wm*32,    k0, lane);
        lda(a[1], sa, wm*32+16, k0, lane);
        #pragma unroll
        for (int ni=0; ni<8; ni++){
            ldb_kn(b, sb, wn*64+ni*8, k0, lane);
            mma16816(acc2[0][ni], a[0], b);
            mma16816(acc2[1][ni], a[1], b);
        }
    }
    __syncthreads();

    // ---- add b2, stash fp32, L2-normalize per row, write bf16 ----
    float* F = (float*)sm;                            // 128 x PITCHF floats (reuses both tiles)
    #pragma unroll
    for (int mi=0; mi<2; mi++)
        #pragma unroll
        for (int ni=0; ni<8; ni++){
            int r0 = wm*32 + mi*16 + (lane>>2);
            int c  = wn*64 + ni*8 + 2*(lane&3);
            F[r0*PITCHF + c]       = acc2[mi][ni][0] + b2g[c];
            F[r0*PITCHF + c + 1]   = acc2[mi][ni][1] + b2g[c+1];
            F[(r0+8)*PITCHF + c]     = acc2[mi][ni][2] + b2g[c];
            F[(r0+8)*PITCHF + c + 1] = acc2[mi][ni][3] + b2g[c+1];
        }
    __syncthreads();

    float scale = which ? 1.44269504088896341f * expf(-lt[0]) : 1.0f;  // log2(e)/temp
    #pragma unroll 1
    for (int rr=0; rr<16; rr++){
        int r = warp*16 + rr;
        float4 v = *(const float4*)(F + r*PITCHF + lane*4);
        float s = v.x*v.x + v.y*v.y + v.z*v.z + v.w*v.w;
        #pragma unroll
        for (int o=16; o; o>>=1) s += __shfl_xor_sync(0xffffffffu, s, o);
        float inv = scale / fmaxf(sqrtf(s), 1e-12f);
        __nv_bfloat162* dst = (__nv_bfloat162*)(E + (size_t)(rowbase+r)*PD + lane*4);
        dst[0] = __floats2bfloat162_rn(v.x*inv, v.y*inv);
        dst[1] = __floats2bfloat162_rn(v.z*inv, v.w*inv);
    }
}

// ---------------- logits tile kernel: exp2(ip @ np^T) -> row/col sums ----------------
// grid (128,128); CTA = 128x128 logits tile; 256 threads, warps 4(m)x2(n).
__global__ __launch_bounds__(256,2)
void logits_kernel()
{
    extern __shared__ __nv_bfloat16 sm[];
    __nv_bfloat16* SA = sm;
    __nv_bfloat16* SB = sm + 128*PITCH;
    const int tid = threadIdx.x, lane = tid & 31, warp = tid >> 5;
    const int wm = warp & 3, wn = warp >> 2;
    const int rowA = blockIdx.y * 128;   // ip rows
    const int rowB = blockIdx.x * 128;   // np rows (cols of logits)

    #pragma unroll
    for (int it=0; it<8; it++){
        int idx = it*256 + tid;
        int r = idx >> 4, c8 = (idx & 15)*8;
        *(uint4*)(SA + r*PITCH + c8) = *(const uint4*)(g_ip + (size_t)(rowA+r)*PD + c8);
        *(uint4*)(SB + r*PITCH + c8) = *(const uint4*)(g_np + (size_t)(rowB+r)*PD + c8);
    }
    __syncthreads();

    float acc[2][8][4];
    #pragma unroll
    for (int i=0;i<2;i++)
        #pragma unroll
        for (int j=0;j<8;j++)
            #pragma unroll
            for (int k=0;k<4;k++) acc[i][j][k] = 0.f;

    const uint32_t sa = smem_u32(SA), sb = smem_u32(SB);
    #pragma unroll
    for (int ks=0; ks<8; ks++){
        int k0 = ks*16;
        uint32_t a[2][4], b[2];
        lda(a[0], sa, wm*32,    k0, lane);
        lda(a[1], sa, wm*32+16, k0, lane);
        #pragma unroll
        for (int ni=0; ni<8; ni++){
            ldb_nk(b, sb, wn*64+ni*8, k0, lane);
            mma16816(acc[0][ni], a[0], b);
            mma16816(acc[1][ni], a[1], b);
        }
    }

    // exp2 + partial row/col sums
    float rsum[2][2];
    float csum[8][2];
    #pragma unroll
    for (int i=0;i<2;i++) rsum[i][0] = rsum[i][1] = 0.f;
    #pragma unroll
    for (int i=0;i<8;i++) csum[i][0] = csum[i][1] = 0.f;

    #pragma unroll
    for (int mi=0; mi<2; mi++)
        #pragma unroll
        for (int ni=0; ni<8; ni++){
            float p0 = ex2f(acc[mi][ni][0]);
            float p1 = ex2f(acc[mi][ni][1]);
            float p2 = ex2f(acc[mi][ni][2]);
            float p3 = ex2f(acc[mi][ni][3]);
            rsum[mi][0] += p0 + p1;       // row r0
            rsum[mi][1] += p2 + p3;       // row r0+8
            csum[ni][0] += p0 + p2;       // col c
            csum[ni][1] += p1 + p3;       // col c+1
        }

    // rows: lanes with same l>>2 share a row; reduce over l&3
    #pragma unroll
    for (int mi=0; mi<2; mi++)
        #pragma unroll
        for (int rr=0; rr<2; rr++){
            float v = rsum[mi][rr];
            v += __shfl_xor_sync(0xffffffffu, v, 1);
            v += __shfl_xor_sync(0xffffffffu, v, 2);
            if ((lane & 3) == 0)
                atomicAdd(&g_rowsum[rowA + wm*32 + mi*16 + rr*8 + (lane>>2)], v);
        }
    // cols: lanes with same l&3 share a col; reduce over l>>2
    #pragma unroll
    for (int ni=0; ni<8; ni++)
        #pragma unroll
        for (int jj=0; jj<2; jj++){
            float v = csum[ni][jj];
            v += __shfl_xor_sync(0xffffffffu, v, 4);
            v += __shfl_xor_sync(0xffffffffu, v, 8);
            v += __shfl_xor_sync(0xffffffffu, v, 16);
            if (lane < 4)
                atomicAdd(&g_colsum[rowB + wn*64 + ni*8 + 2*lane + jj], v);
        }
}

// ---------------- loss assembly ----------------
// val_i = 0.5*(ln rowsum_i + ln colsum_i) - diag_i ; diag_i = ln2 * dot(ip_i, np_i)
__global__ void loss_part()
{
    __shared__ float red[256];
    int row = blockIdx.x*256 + threadIdx.x;
    const uint4* pi = (const uint4*)(g_ip + (size_t)row*PD);
    const uint4* pn = (const uint4*)(g_np + (size_t)row*PD);
    float dot = 0.f;
    #pragma unroll
    for (int i=0; i<16; i++){
        uint4 a = pi[i], b = pn[i];
        const __nv_bfloat162* pa = (const __nv_bfloat162*)&a;
        const __nv_bfloat162* pb = (const __nv_bfloat162*)&b;
        #pragma unroll
        for (int j=0; j<4; j++){
            float2 fa = __bfloat1622float2(pa[j]);
            float2 fb = __bfloat1622float2(pb[j]);
            dot += fa.x*fb.x + fa.y*fb.y;
        }
    }
    float val = 0.5f*(logf(g_rowsum[row]) + logf(g_colsum[row]))
              - dot * 0.69314718055994531f;
    red[threadIdx.x] = val;
    __syncthreads();
    #pragma unroll
    for (int o=128; o; o>>=1){
        if (threadIdx.x < o) red[threadIdx.x] += red[threadIdx.x + o];
        __syncthreads();
    }
    if (threadIdx.x == 0) g_part[blockIdx.x] = red[0];
}

__global__ void loss_final(float* out)
{
    int l = threadIdx.x;
    float v = g_part[l] + g_part[l+32];
    #pragma unroll
    for (int o=16; o; o>>=1) v += __shfl_xor_sync(0xffffffffu, v, o);
    if (l == 0) out[0] = v * (1.0f/16384.0f);
}

// ---------------- launcher ----------------
extern "C" void kernel_launch(void* const* d_in, const int* in_sizes, int n_in,
                              void* d_out, int out_size)
{
    (void)in_sizes; (void)n_in; (void)out_size;
    const float* img = (const float*)d_in[0];
    const float* num = (const float*)d_in[1];
    const float* Wi1 = (const float*)d_in[2];
    const float* bi1 = (const float*)d_in[3];
    const float* Wi2 = (const float*)d_in[4];
    const float* bi2 = (const float*)d_in[5];
    const float* Wn1 = (const float*)d_in[6];
    const float* bn1 = (const float*)d_in[7];
    const float* Wn2 = (const float*)d_in[8];
    const float* bn2 = (const float*)d_in[9];
    const float* lt  = (const float*)d_in[10];
    float* out = (float*)d_out;

    cudaFuncSetAttribute(mlp_norm<2048>, cudaFuncAttributeMaxDynamicSharedMemorySize, SMEM_BYTES);
    cudaFuncSetAttribute(mlp_norm<256>,  cudaFuncAttributeMaxDynamicSharedMemorySize, SMEM_BYTES);
    cudaFuncSetAttribute(logits_kernel,  cudaFuncAttributeMaxDynamicSharedMemorySize, SMEM_BYTES);

    convert_weights<<<1024, 256>>>(Wi1, Wi2, Wn1, Wn2);
    mlp_norm<2048><<<128, 256, SMEM_BYTES>>>(img, bi1, bi2, lt, 0);
    mlp_norm<256> <<<128, 256, SMEM_BYTES>>>(num, bn1, bn2, lt, 1);
    zero_sums<<<128, 256>>>();
    logits_kernel<<<dim3(128,128), 256, SMEM_BYTES>>>();
    loss_part<<<64, 256>>>();
    loss_final<<<1, 32>>>(out);
}

// round 4
// speedup vs baseline: 1.0041x; 1.0041x over previous
#include <cuda_runtime.h>
#include <cuda_bf16.h>
#include <stdint.h>

#define NB     16384
#define PD     128
#define PITCH  136     // bf16 per smem row for MLP kernels (128 + 8 pad)
#define PITCHF 132
#define SMEM_BYTES (2*128*PITCH*2)    // 69632 B (MLP kernels)
#define PB     144                    // byte pitch for fp8 logits tiles (128 + 16)
#define TILEB  (128*PB)               // 18432 B per 128x128 fp8 tile
#define LOG_SMEM (4*TILEB)            // A0,B0,A1,B1 = 73728 B

// ---------------- device scratch (allocation-free) ----------------
__device__ __nv_bfloat16 g_Wi1[2048*PD];
__device__ __nv_bfloat16 g_Wi2[PD*PD];
__device__ __nv_bfloat16 g_Wn1[256*PD];
__device__ __nv_bfloat16 g_Wn2[PD*PD];
__device__ __nv_bfloat16 g_ip[NB*PD];   // normalized img embeddings (bf16, for diag)
__device__ __nv_bfloat16 g_np[NB*PD];   // normalized num embeddings * log2e/temp (bf16, for diag)
__device__ uint8_t g_ip8[NB*PD];        // e4m3 img embeddings
__device__ uint8_t g_np8[NB*PD];        // e4m3 num embeddings * log2e/temp
__device__ float g_rowsum[NB];
__device__ float g_colsum[NB];
__device__ float g_part[64];

// ---------------- asm helpers ----------------
static __device__ __forceinline__ uint32_t smem_u32(const void* p){
    return (uint32_t)__cvta_generic_to_shared(p);
}
static __device__ __forceinline__ void ldsm_x4(uint32_t r[4], uint32_t a){
    asm volatile("ldmatrix.sync.aligned.m8n8.x4.shared.b16 {%0,%1,%2,%3},[%4];"
        : "=r"(r[0]),"=r"(r[1]),"=r"(r[2]),"=r"(r[3]) : "r"(a));
}
static __device__ __forceinline__ void ldsm_x2(uint32_t r[2], uint32_t a){
    asm volatile("ldmatrix.sync.aligned.m8n8.x2.shared.b16 {%0,%1},[%2];"
        : "=r"(r[0]),"=r"(r[1]) : "r"(a));
}
static __device__ __forceinline__ void ldsm_x2t(uint32_t r[2], uint32_t a){
    asm volatile("ldmatrix.sync.aligned.m8n8.x2.trans.shared.b16 {%0,%1},[%2];"
        : "=r"(r[0]),"=r"(r[1]) : "r"(a));
}
static __device__ __forceinline__ void mma16816(float c[4], const uint32_t a[4], const uint32_t b[2]){
    asm("mma.sync.aligned.m16n8k16.row.col.f32.bf16.bf16.f32 "
        "{%0,%1,%2,%3},{%4,%5,%6,%7},{%8,%9},{%0,%1,%2,%3};"
        : "+f"(c[0]),"+f"(c[1]),"+f"(c[2]),"+f"(c[3])
        : "r"(a[0]),"r"(a[1]),"r"(a[2]),"r"(a[3]),"r"(b[0]),"r"(b[1]));
}
static __device__ __forceinline__ void mma_fp8(float c[4], const uint32_t a[4], const uint32_t b[2]){
    asm("mma.sync.aligned.m16n8k32.row.col.f32.e4m3.e4m3.f32 "
        "{%0,%1,%2,%3},{%4,%5,%6,%7},{%8,%9},{%0,%1,%2,%3};"
        : "+f"(c[0]),"+f"(c[1]),"+f"(c[2]),"+f"(c[3])
        : "r"(a[0]),"r"(a[1]),"r"(a[2]),"r"(a[3]),"r"(b[0]),"r"(b[1]));
}
static __device__ __forceinline__ float ex2f(float x){
    float r; asm("ex2.approx.f32 %0,%1;" : "=f"(r) : "f"(x)); return r;
}
static __device__ __forceinline__ uint32_t pack_e4m3(float x0,float x1,float x2,float x3){
    uint32_t r;
    asm("{.reg .b16 lo, hi;\n\t"
        "cvt.rn.satfinite.e4m3x2.f32 lo, %2, %1;\n\t"
        "cvt.rn.satfinite.e4m3x2.f32 hi, %4, %3;\n\t"
        "mov.b32 %0, {lo, hi};}" : "=r"(r) : "f"(x0),"f"(x1),"f"(x2),"f"(x3));
    return r;
}
#define CP16(dst, src) asm volatile("cp.async.cg.shared.global [%0],[%1],16;" \
    :: "r"(dst), "l"(src) : "memory")
#define CP_COMMIT() asm volatile("cp.async.commit_group;" ::: "memory")
#define CP_WAIT1()  asm volatile("cp.async.wait_group 1;" ::: "memory")

// bf16 fragment helpers (MLP kernels, element pitch PITCH)
static __device__ __forceinline__ void lda(uint32_t a[4], uint32_t base, int m0, int k0, int lane){
    int row = m0 + (lane & 7) + ((lane >> 3) & 1) * 8;
    int kk  = k0 + ((lane >> 4) << 3);
    ldsm_x4(a, base + (uint32_t)(row*PITCH + kk)*2u);
}
static __device__ __forceinline__ void ldb_kn(uint32_t b[2], uint32_t base, int n0, int k0, int lane){
    int row = k0 + (lane & 15);
    ldsm_x2t(b, base + (uint32_t)(row*PITCH + n0)*2u);
}
// fp8 fragment helpers (logits kernel, byte pitch PB)
static __device__ __forceinline__ void lda8(uint32_t a[4], uint32_t base, int m0, int k0b, int lane){
    int row = m0 + (lane & 7) + ((lane >> 3) & 1) * 8;
    int cb  = k0b + ((lane >> 4) << 4);
    ldsm_x4(a, base + (uint32_t)(row*PB + cb));
}
static __device__ __forceinline__ void ldb8(uint32_t b[2], uint32_t base, int n0, int k0b, int lane){
    int l = lane & 15;
    int row = n0 + (l & 7);
    int cb  = k0b + ((l >> 3) << 4);
    ldsm_x2(b, base + (uint32_t)(row*PB + cb));
}

// ---------------- prep kernels ----------------
__global__ void convert_small(const float* __restrict__ Wi2, const float* __restrict__ Wn1,
                              const float* __restrict__ Wn2){
    int i = blockIdx.x*blockDim.x + threadIdx.x;    // 32768
    if (i < PD*PD){ g_Wi2[i] = __float2bfloat16(Wi2[i]); g_Wn2[i] = __float2bfloat16(Wn2[i]); }
    g_Wn1[i] = __float2bfloat16(Wn1[i]);
    if (i < NB){ g_rowsum[i] = 0.f; g_colsum[i] = 0.f; }
}
__global__ void convert_big(const float* __restrict__ Wi1){
    int i = blockIdx.x*blockDim.x + threadIdx.x;    // 262144
    g_Wi1[i] = __float2bfloat16(Wi1[i]);
}

// ---------------- fused 2-layer MLP + ReLU + L2-norm (bf16 HMMA) ----------------
template<int D>
__global__ __launch_bounds__(256)
void mlp_norm(const float* __restrict__ X,
              const float* __restrict__ b1g,
              const float* __restrict__ b2g,
              const float* __restrict__ lt,
              int which)                  // 0 = img, 1 = num (scaled)
{
    extern __shared__ __nv_bfloat16 sm[];
    __nv_bfloat16* SA = sm;
    __nv_bfloat16* SB = sm + 128*PITCH;
    const __nv_bfloat16* W1 = which ? g_Wn1 : g_Wi1;
    const __nv_bfloat16* W2 = which ? g_Wn2 : g_Wi2;
    __nv_bfloat16*       E  = which ? g_np  : g_ip;
    uint8_t*             E8 = which ? g_np8 : g_ip8;

    const int tid = threadIdx.x, lane = tid & 31, warp = tid >> 5;
    const int wm = warp & 3, wn = warp >> 2;
    const int rowbase = blockIdx.x * 128;
    const uint32_t sa = smem_u32(SA), sb = smem_u32(SB);

    float acc1[2][8][4];
    #pragma unroll
    for (int i=0;i<2;i++)
        #pragma unroll
        for (int j=0;j<8;j++)
            #pragma unroll
            for (int k=0;k<4;k++) acc1[i][j][k] = 0.f;

    for (int kc = 0; kc < D/64; kc++){
        __syncthreads();
        #pragma unroll
        for (int it=0; it<8; it++){
            int idx = it*256 + tid;
            int r = idx >> 4, c4 = idx & 15;
            float4 v = *(const float4*)(X + (size_t)(rowbase+r)*D + kc*64 + c4*4);
            __nv_bfloat162* dst = (__nv_bfloat162*)(SA + r*PITCH + c4*4);
            dst[0] = __floats2bfloat162_rn(v.x, v.y);
            dst[1] = __floats2bfloat162_rn(v.z, v.w);
        }
        #pragma unroll
        for (int it=0; it<4; it++){
            int idx = it*256 + tid;
            int r = idx >> 4, c8 = (idx & 15)*8;
            *(uint4*)(SB + r*PITCH + c8) = *(const uint4*)(W1 + (size_t)(kc*64+r)*PD + c8);
        }
        __syncthreads();
        #pragma unroll
        for (int ks=0; ks<4; ks++){
            int k0 = ks*16;
            uint32_t a[2][4], b[2];
            lda(a[0], sa, wm*32,    k0, lane);
            lda(a[1], sa, wm*32+16, k0, lane);
            #pragma unroll
            for (int ni=0; ni<8; ni++){
                ldb_kn(b, sb, wn*64+ni*8, k0, lane);
                mma16816(acc1[0][ni], a[0], b);
                mma16816(acc1[1][ni], a[1], b);
            }
        }
    }
    __syncthreads();

    #pragma unroll
    for (int mi=0; mi<2; mi++)
        #pragma unroll
        for (int ni=0; ni<8; ni++){
            int r0 = wm*32 + mi*16 + (lane>>2);
            int c  = wn*64 + ni*8 + 2*(lane&3);
            float ba = b1g[c], bb = b1g[c+1];
            *(__nv_bfloat162*)(SA + r0*PITCH + c) =
                __floats2bfloat162_rn(fmaxf(acc1[mi][ni][0]+ba,0.f), fmaxf(acc1[mi][ni][1]+bb,0.f));
            *(__nv_bfloat162*)(SA + (r0+8)*PITCH + c) =
                __floats2bfloat162_rn(fmaxf(acc1[mi][ni][2]+ba,0.f), fmaxf(acc1[mi][ni][3]+bb,0.f));
        }
    #pragma unroll
    for (int it=0; it<8; it++){
        int idx = it*256 + tid;
        int r = idx >> 4, c8 = (idx & 15)*8;
        *(uint4*)(SB + r*PITCH + c8) = *(const uint4*)(W2 + (size_t)r*PD + c8);
    }
    __syncthreads();

    float acc2[2][8][4];
    #pragma unroll
    for (int i=0;i<2;i++)
        #pragma unroll
        for (int j=0;j<8;j++)
            #pragma unroll
            for (int k=0;k<4;k++) acc2[i][j][k] = 0.f;

    #pragma unroll
    for (int ks=0; ks<8; ks++){
        int k0 = ks*16;
        uint32_t a[2][4], b[2];
        lda(a[0], sa, wm*32,    k0, lane);
        lda(a[1], sa, wm*32+16, k0, lane);
        #pragma unroll
        for (int ni=0; ni<8; ni++){
            ldb_kn(b, sb, wn*64+ni*8, k0, lane);
            mma16816(acc2[0][ni], a[0], b);
            mma16816(acc2[1][ni], a[1], b);
        }
    }
    __syncthreads();

    float* F = (float*)sm;
    #pragma unroll
    for (int mi=0; mi<2; mi++)
        #pragma unroll
        for (int ni=0; ni<8; ni++){
            int r0 = wm*32 + mi*16 + (lane>>2);
            int c  = wn*64 + ni*8 + 2*(lane&3);
            F[r0*PITCHF + c]         = acc2[mi][ni][0] + b2g[c];
            F[r0*PITCHF + c + 1]     = acc2[mi][ni][1] + b2g[c+1];
            F[(r0+8)*PITCHF + c]     = acc2[mi][ni][2] + b2g[c];
            F[(r0+8)*PITCHF + c + 1] = acc2[mi][ni][3] + b2g[c+1];
        }
    __syncthreads();

    float scale = which ? 1.44269504088896341f * expf(-lt[0]) : 1.0f;
    #pragma unroll 1
    for (int rr=0; rr<16; rr++){
        int r = warp*16 + rr;
        float4 v = *(const float4*)(F + r*PITCHF + lane*4);
        float s = v.x*v.x + v.y*v.y + v.z*v.z + v.w*v.w;
        #pragma unroll
        for (int o=16; o; o>>=1) s += __shfl_xor_sync(0xffffffffu, s, o);
        float inv = scale / fmaxf(sqrtf(s), 1e-12f);
        float e0 = v.x*inv, e1 = v.y*inv, e2 = v.z*inv, e3 = v.w*inv;
        __nv_bfloat162* dst = (__nv_bfloat162*)(E + (size_t)(rowbase+r)*PD + lane*4);
        dst[0] = __floats2bfloat162_rn(e0, e1);
        dst[1] = __floats2bfloat162_rn(e2, e3);
        *(uint32_t*)(E8 + (size_t)(rowbase+r)*PD + lane*4) = pack_e4m3(e0, e1, e2, e3);
    }
}

// ---------------- fp8 logits kernel ----------------
// Persistent 296 CTAs (2/SM); each loops over 128x128 logit tiles with
// cp.async double-buffered staging. acc = logit*log2e in registers; epilogue
// ex2 + row/col partial sums (atomics).
__global__ __launch_bounds__(256, 2)
void logits_fp8()
{
    extern __shared__ uint8_t dyn8[];
    const uint32_t base = smem_u32(dyn8);
    const int tid = threadIdx.x, lane = tid & 31, warp = tid >> 5;
    const int wm = warp & 3, wn = warp >> 2;

    int t = blockIdx.x;
    const int stride = gridDim.x;

    // prologue: stage tile t into buffer 0
    {
        const int rowA = (t & 127) * 128, rowB = (t >> 7) * 128;
        const uint8_t* gA = g_ip8 + (size_t)rowA * PD;
        const uint8_t* gB = g_np8 + (size_t)rowB * PD;
        #pragma unroll
        for (int it=0; it<4; it++){
            int idx = it*256 + tid;
            int r = idx >> 3, c = (idx & 7)*16;
            CP16(base + r*PB + c,            gA + r*PD + c);
            CP16(base + TILEB*1 + r*PB + c,  gB + r*PD + c);
        }
    }
    CP_COMMIT();

    int buf = 0;
    for (; t < 16384; t += stride){
        // prefetch next tile into other buffer
        int tn = t + stride;
        if (tn < 16384){
            const int rowA = (tn & 127) * 128, rowB = (tn >> 7) * 128;
            const uint8_t* gA = g_ip8 + (size_t)rowA * PD;
            const uint8_t* gB = g_np8 + (size_t)rowB * PD;
            const uint32_t bA = base + (buf^1)*2*TILEB;
            #pragma unroll
            for (int it=0; it<4; it++){
                int idx = it*256 + tid;
                int r = idx >> 3, c = (idx & 7)*16;
                CP16(bA + r*PB + c,          gA + r*PD + c);
                CP16(bA + TILEB + r*PB + c,  gB + r*PD + c);
            }
        }
        CP_COMMIT();
        CP_WAIT1();            // current tile's buffer complete (<=1 group pending)
        __syncthreads();

        const uint32_t sA = base + buf*2*TILEB;
        const uint32_t sB = sA + TILEB;
        const int rowA = (t & 127) * 128, rowB = (t >> 7) * 128;

        float acc[2][8][4];
        #pragma unroll
        for (int i=0;i<2;i++)
            #pragma unroll
            for (int j=0;j<8;j++)
                #pragma unroll
                for (int k=0;k<4;k++) acc[i][j][k] = 0.f;

        #pragma unroll
        for (int ks=0; ks<4; ks++){
            int k0b = ks*32;
            uint32_t a[2][4], b[2];
            lda8(a[0], sA, wm*32,    k0b, lane);
            lda8(a[1], sA, wm*32+16, k0b, lane);
            #pragma unroll
            for (int ni=0; ni<8; ni++){
                ldb8(b, sB, wn*64+ni*8, k0b, lane);
                mma_fp8(acc[0][ni], a[0], b);
                mma_fp8(acc[1][ni], a[1], b);
            }
        }

        // epilogue: exp2 + row/col partial sums (verified in R2)
        float rsum[2][2];
        float csum[8][2];
        #pragma unroll
        for (int i=0;i<2;i++) rsum[i][0] = rsum[i][1] = 0.f;
        #pragma unroll
        for (int i=0;i<8;i++) csum[i][0] = csum[i][1] = 0.f;

        #pragma unroll
        for (int mi=0; mi<2; mi++)
            #pragma unroll
            for (int ni=0; ni<8; ni++){
                float p0 = ex2f(acc[mi][ni][0]);
                float p1 = ex2f(acc[mi][ni][1]);
                float p2 = ex2f(acc[mi][ni][2]);
                float p3 = ex2f(acc[mi][ni][3]);
                rsum[mi][0] += p0 + p1;
                rsum[mi][1] += p2 + p3;
                csum[ni][0] += p0 + p2;
                csum[ni][1] += p1 + p3;
            }

        #pragma unroll
        for (int mi=0; mi<2; mi++)
            #pragma unroll
            for (int rr=0; rr<2; rr++){
                float v = rsum[mi][rr];
                v += __shfl_xor_sync(0xffffffffu, v, 1);
                v += __shfl_xor_sync(0xffffffffu, v, 2);
                if ((lane & 3) == 0)
                    atomicAdd(&g_rowsum[rowA + wm*32 + mi*16 + rr*8 + (lane>>2)], v);
            }
        #pragma unroll
        for (int ni=0; ni<8; ni++)
            #pragma unroll
            for (int jj=0; jj<2; jj++){
                float v = csum[ni][jj];
                v += __shfl_xor_sync(0xffffffffu, v, 4);
                v += __shfl_xor_sync(0xffffffffu, v, 8);
                v += __shfl_xor_sync(0xffffffffu, v, 16);
                if (lane < 4)
                    atomicAdd(&g_colsum[rowB + wn*64 + ni*8 + 2*lane + jj], v);
            }

        __syncthreads();   // all reads of buf done before it is re-staged
        buf ^= 1;
    }
}

// ---------------- loss assembly ----------------
__global__ void loss_part()
{
    __shared__ float red[256];
    int row = blockIdx.x*256 + threadIdx.x;
    const uint4* pi = (const uint4*)(g_ip + (size_t)row*PD);
    const uint4* pn = (const uint4*)(g_np + (size_t)row*PD);
    float dot = 0.f;
    #pragma unroll
    for (int i=0; i<16; i++){
        uint4 a = pi[i], b = pn[i];
        const __nv_bfloat162* pa = (const __nv_bfloat162*)&a;
        const __nv_bfloat162* pb = (const __nv_bfloat162*)&b;
        #pragma unroll
        for (int j=0; j<4; j++){
            float2 fa = __bfloat1622float2(pa[j]);
            float2 fb = __bfloat1622float2(pb[j]);
            dot += fa.x*fb.x + fa.y*fb.y;
        }
    }
    float val = 0.5f*(logf(g_rowsum[row]) + logf(g_colsum[row]))
              - dot * 0.69314718055994531f;
    red[threadIdx.x] = val;
    __syncthreads();
    #pragma unroll
    for (int o=128; o; o>>=1){
        if (threadIdx.x < o) red[threadIdx.x] += red[threadIdx.x + o];
        __syncthreads();
    }
    if (threadIdx.x == 0) g_part[blockIdx.x] = red[0];
}

__global__ void loss_final(float* out)
{
    int l = threadIdx.x;
    float v = g_part[l] + g_part[l+32];
    #pragma unroll
    for (int o=16; o; o>>=1) v += __shfl_xor_sync(0xffffffffu, v, o);
    if (l == 0) out[0] = v * (1.0f/16384.0f);
}

// ---------------- launcher ----------------
extern "C" void kernel_launch(void* const* d_in, const int* in_sizes, int n_in,
                              void* d_out, int out_size)
{
    (void)in_sizes; (void)n_in; (void)out_size;
    const float* img = (const float*)d_in[0];
    const float* num = (const float*)d_in[1];
    const float* Wi1 = (const float*)d_in[2];
    const float* bi1 = (const float*)d_in[3];
    const float* Wi2 = (const float*)d_in[4];
    const float* bi2 = (const float*)d_in[5];
    const float* Wn1 = (const float*)d_in[6];
    const float* bn1 = (const float*)d_in[7];
    const float* Wn2 = (const float*)d_in[8];
    const float* bn2 = (const float*)d_in[9];
    const float* lt  = (const float*)d_in[10];
    float* out = (float*)d_out;

    cudaFuncSetAttribute(mlp_norm<2048>, cudaFuncAttributeMaxDynamicSharedMemorySize, SMEM_BYTES);
    cudaFuncSetAttribute(mlp_norm<256>,  cudaFuncAttributeMaxDynamicSharedMemorySize, SMEM_BYTES);
    cudaFuncSetAttribute(logits_fp8,     cudaFuncAttributeMaxDynamicSharedMemorySize, LOG_SMEM);

    convert_small<<<128, 256>>>(Wi2, Wn1, Wn2);                       // 1
    convert_big<<<1024, 256>>>(Wi1);                                  // 2
    mlp_norm<256> <<<128, 256, SMEM_BYTES>>>(num, bn1, bn2, lt, 1);   // 3
    mlp_norm<2048><<<128, 256, SMEM_BYTES>>>(img, bi1, bi2, lt, 0);   // 4
    logits_fp8<<<296, 256, LOG_SMEM>>>();                             // 5
    loss_part<<<64, 256>>>();                                         // 6
    loss_final<<<1, 32>>>(out);                                       // 7
}

// round 5
// speedup vs baseline: 1.4422x; 1.4363x over previous
#include <cuda_runtime.h>
#include <cuda_bf16.h>
#include <stdint.h>

#define NB     16384
#define PD     128
#define PITCH  136                    // bf16 pitch for weight/H tiles (128+8)
#define XPITCH 72                     // fp32 pitch for X staging (conflict-free frag loads)
#define PITCHF 132
#define XFBYTES (128*XPITCH*4)        // 36864 per buffer
#define WBBYTES (64*PITCH*2)          // 17408 per buffer
#define MLP_SMEM (2*XFBYTES + 2*WBBYTES)   // 108544
#define PB     144                    // byte pitch fp8 logits tiles
#define TILEB  (128*PB)               // 18432
#define LOG_SMEM (3*TILEB)            // A0, A1, B = 55296

// ---------------- device scratch ----------------
__device__ __nv_bfloat16 g_Wi1[2048*PD];
__device__ __nv_bfloat16 g_Wi2[PD*PD];
__device__ __nv_bfloat16 g_Wn1[256*PD];
__device__ __nv_bfloat16 g_Wn2[PD*PD];
__device__ __nv_bfloat16 g_ip[NB*PD];
__device__ __nv_bfloat16 g_np[NB*PD];
__device__ uint8_t g_ip8[NB*PD];
__device__ uint8_t g_np8[NB*PD];
__device__ float g_rowsum[NB];
__device__ float g_colsum[NB];
__device__ float g_part[64];

// ---------------- asm helpers ----------------
static __device__ __forceinline__ uint32_t smem_u32(const void* p){
    return (uint32_t)__cvta_generic_to_shared(p);
}
static __device__ __forceinline__ void ldsm_x4(uint32_t r[4], uint32_t a){
    asm volatile("ldmatrix.sync.aligned.m8n8.x4.shared.b16 {%0,%1,%2,%3},[%4];"
        : "=r"(r[0]),"=r"(r[1]),"=r"(r[2]),"=r"(r[3]) : "r"(a));
}
static __device__ __forceinline__ void ldsm_x2(uint32_t r[2], uint32_t a){
    asm volatile("ldmatrix.sync.aligned.m8n8.x2.shared.b16 {%0,%1},[%2];"
        : "=r"(r[0]),"=r"(r[1]) : "r"(a));
}
static __device__ __forceinline__ void ldsm_x2t(uint32_t r[2], uint32_t a){
    asm volatile("ldmatrix.sync.aligned.m8n8.x2.trans.shared.b16 {%0,%1},[%2];"
        : "=r"(r[0]),"=r"(r[1]) : "r"(a));
}
static __device__ __forceinline__ void mma16816(float c[4], const uint32_t a[4], const uint32_t b[2]){
    asm("mma.sync.aligned.m16n8k16.row.col.f32.bf16.bf16.f32 "
        "{%0,%1,%2,%3},{%4,%5,%6,%7},{%8,%9},{%0,%1,%2,%3};"
        : "+f"(c[0]),"+f"(c[1]),"+f"(c[2]),"+f"(c[3])
        : "r"(a[0]),"r"(a[1]),"r"(a[2]),"r"(a[3]),"r"(b[0]),"r"(b[1]));
}
static __device__ __forceinline__ void mma_fp8(float c[4], const uint32_t a[4], const uint32_t b[2]){
    asm("mma.sync.aligned.m16n8k32.row.col.f32.e4m3.e4m3.f32 "
        "{%0,%1,%2,%3},{%4,%5,%6,%7},{%8,%9},{%0,%1,%2,%3};"
        : "+f"(c[0]),"+f"(c[1]),"+f"(c[2]),"+f"(c[3])
        : "r"(a[0]),"r"(a[1]),"r"(a[2]),"r"(a[3]),"r"(b[0]),"r"(b[1]));
}
static __device__ __forceinline__ float ex2f(float x){
    float r; asm("ex2.approx.f32 %0,%1;" : "=f"(r) : "f"(x)); return r;
}
static __device__ __forceinline__ uint32_t pack_e4m3(float x0,float x1,float x2,float x3){
    uint32_t r;
    asm("{.reg .b16 lo, hi;\n\t"
        "cvt.rn.satfinite.e4m3x2.f32 lo, %2, %1;\n\t"
        "cvt.rn.satfinite.e4m3x2.f32 hi, %4, %3;\n\t"
        "mov.b32 %0, {lo, hi};}" : "=r"(r) : "f"(x0),"f"(x1),"f"(x2),"f"(x3));
    return r;
}
#define CP16(dst, src) asm volatile("cp.async.cg.shared.global [%0],[%1],16;" \
    :: "r"(dst), "l"(src) : "memory")
#define CP_COMMIT() asm volatile("cp.async.commit_group;" ::: "memory")
#define CP_WAIT0()  asm volatile("cp.async.wait_group 0;" ::: "memory")
#define CP_WAIT1()  asm volatile("cp.async.wait_group 1;" ::: "memory")

// bf16 fragment helpers (pitch PITCH)
static __device__ __forceinline__ void lda(uint32_t a[4], uint32_t base, int m0, int k0, int lane){
    int row = m0 + (lane & 7) + ((lane >> 3) & 1) * 8;
    int kk  = k0 + ((lane >> 4) << 3);
    ldsm_x4(a, base + (uint32_t)(row*PITCH + kk)*2u);
}
static __device__ __forceinline__ void ldb_kn(uint32_t b[2], uint32_t base, int n0, int k0, int lane){
    int row = k0 + (lane & 15);
    ldsm_x2t(b, base + (uint32_t)(row*PITCH + n0)*2u);
}
// A fragment built directly from fp32 smem (pitch XPITCH)
static __device__ __forceinline__ uint32_t f2frag(const float* XF, int r, int c){
    float2 v = *(const float2*)(XF + r*XPITCH + c);
    __nv_bfloat162 h = __floats2bfloat162_rn(v.x, v.y);
    return *(uint32_t*)&h;
}
// fp8 fragment helpers (byte pitch PB)
static __device__ __forceinline__ void lda8(uint32_t a[4], uint32_t base, int m0, int k0b, int lane){
    int row = m0 + (lane & 7) + ((lane >> 3) & 1) * 8;
    int cb  = k0b + ((lane >> 4) << 4);
    ldsm_x4(a, base + (uint32_t)(row*PB + cb));
}
static __device__ __forceinline__ void ldb8(uint32_t b[2], uint32_t base, int n0, int k0b, int lane){
    int l = lane & 15;
    int row = n0 + (l & 7);
    int cb  = k0b + ((l >> 3) << 4);
    ldsm_x2(b, base + (uint32_t)(row*PB + cb));
}

// ---------------- prep kernels ----------------
__global__ void convert_small(const float* __restrict__ Wi2, const float* __restrict__ Wn1,
                              const float* __restrict__ Wn2){
    int i = blockIdx.x*blockDim.x + threadIdx.x;    // 32768
    if (i < PD*PD){ g_Wi2[i] = __float2bfloat16(Wi2[i]); g_Wn2[i] = __float2bfloat16(Wn2[i]); }
    g_Wn1[i] = __float2bfloat16(Wn1[i]);
    if (i < NB){ g_rowsum[i] = 0.f; g_colsum[i] = 0.f; }
}
__global__ void convert_big(const float* __restrict__ Wi1){
    int i = blockIdx.x*blockDim.x + threadIdx.x;    // 262144
    g_Wi1[i] = __float2bfloat16(Wi1[i]);
}

// ---------------- merged fused MLP + ReLU + L2-norm (pipelined) ----------------
// grid 256: blocks 0..127 img (D=2048), 128..255 num (D=256). 256 thr, warps 4m x 2n.
__global__ __launch_bounds__(256)
void mlp_all(const float* __restrict__ Ximg, const float* __restrict__ Xnum,
             const float* __restrict__ bi1, const float* __restrict__ bi2,
             const float* __restrict__ bn1, const float* __restrict__ bn2,
             const float* __restrict__ lt)
{
    extern __shared__ char dyn[];
    const int which = blockIdx.x >> 7;
    const int D  = which ? 256 : 2048;
    const int NC = which ? 4 : 32;
    const float* X  = which ? Xnum : Ximg;
    const float* b1g = which ? bn1 : bi1;
    const float* b2g = which ? bn2 : bi2;
    const __nv_bfloat16* W1 = which ? g_Wn1 : g_Wi1;
    const __nv_bfloat16* W2 = which ? g_Wn2 : g_Wi2;
    __nv_bfloat16*       E  = which ? g_np  : g_ip;
    uint8_t*             E8 = which ? g_np8 : g_ip8;

    const int tid = threadIdx.x, lane = tid & 31, warp = tid >> 5;
    const int wm = warp & 3, wn = warp >> 2;
    const int rowbase = (blockIdx.x & 127) * 128;
    const int fr = lane >> 2, fc = 2*(lane & 3);

    char* XFbuf = dyn;                    // 2 x 36864 fp32 tiles
    char* WBbuf = dyn + 2*XFBYTES;        // 2 x 17408 bf16 W1 tiles

    // stage chunk kc into buffer b
    auto stage = [&](int kc, int b){
        uint32_t xd = smem_u32(XFbuf + b*XFBYTES);
        #pragma unroll
        for (int it=0; it<8; it++){
            int seg = it*256 + tid;
            int r = seg >> 4, s = seg & 15;
            CP16(xd + (uint32_t)(r*(XPITCH*4) + s*16),
                 (const char*)(X + (size_t)(rowbase+r)*D + kc*64) + s*16);
        }
        uint32_t wd = smem_u32(WBbuf + b*WBBYTES);
        #pragma unroll
        for (int it=0; it<4; it++){
            int seg = it*256 + tid;
            int r = seg >> 4, s = seg & 15;
            CP16(wd + (uint32_t)(r*(PITCH*2) + s*16),
                 (const char*)(W1 + (size_t)(kc*64+r)*PD) + s*16);
        }
    };

    float acc1[2][8][4];
    #pragma unroll
    for (int i=0;i<2;i++)
        #pragma unroll
        for (int j=0;j<8;j++)
            #pragma unroll
            for (int k=0;k<4;k++) acc1[i][j][k] = 0.f;

    stage(0, 0); CP_COMMIT();

    for (int kc = 0; kc < NC; kc++){
        int buf = kc & 1;
        if (kc+1 < NC){ stage(kc+1, buf^1); CP_COMMIT(); CP_WAIT1(); }
        else          { CP_WAIT0(); }
        __syncthreads();
        const float* XF = (const float*)(XFbuf + buf*XFBYTES);
        const uint32_t wb = smem_u32(WBbuf + buf*WBBYTES);
        #pragma unroll
        for (int ks=0; ks<4; ks++){
            int k0 = ks*16;
            uint32_t a[2][4], b[2];
            #pragma unroll
            for (int mi=0; mi<2; mi++){
                int m0 = wm*32 + mi*16;
                a[mi][0] = f2frag(XF, m0+fr,   k0+fc);
                a[mi][1] = f2frag(XF, m0+fr+8, k0+fc);
                a[mi][2] = f2frag(XF, m0+fr,   k0+fc+8);
                a[mi][3] = f2frag(XF, m0+fr+8, k0+fc+8);
            }
            #pragma unroll
            for (int ni=0; ni<8; ni++){
                ldb_kn(b, wb, wn*64+ni*8, k0, lane);
                mma16816(acc1[0][ni], a[0], b);
                mma16816(acc1[1][ni], a[1], b);
            }
        }
        __syncthreads();
    }

    // bias + relu -> H (bf16, pitch PITCH) at dyn[0..34816); stage W2 at WBbuf
    __nv_bfloat16* H = (__nv_bfloat16*)dyn;
    #pragma unroll
    for (int mi=0; mi<2; mi++)
        #pragma unroll
        for (int ni=0; ni<8; ni++){
            int r0 = wm*32 + mi*16 + fr;
            int c  = wn*64 + ni*8 + fc;
            float ba = b1g[c], bb = b1g[c+1];
            *(__nv_bfloat162*)(H + r0*PITCH + c) =
                __floats2bfloat162_rn(fmaxf(acc1[mi][ni][0]+ba,0.f), fmaxf(acc1[mi][ni][1]+bb,0.f));
            *(__nv_bfloat162*)(H + (r0+8)*PITCH + c) =
                __floats2bfloat162_rn(fmaxf(acc1[mi][ni][2]+ba,0.f), fmaxf(acc1[mi][ni][3]+bb,0.f));
        }
    __nv_bfloat16* W2s = (__nv_bfloat16*)WBbuf;
    #pragma unroll
    for (int it=0; it<8; it++){
        int idx = it*256 + tid;
        int r = idx >> 4, c8 = (idx & 15)*8;
        *(uint4*)(W2s + r*PITCH + c8) = *(const uint4*)(W2 + (size_t)r*PD + c8);
    }
    __syncthreads();

    float acc2[2][8][4];
    #pragma unroll
    for (int i=0;i<2;i++)
        #pragma unroll
        for (int j=0;j<8;j++)
            #pragma unroll
            for (int k=0;k<4;k++) acc2[i][j][k] = 0.f;

    const uint32_t hb = smem_u32(H), wb2 = smem_u32(W2s);
    #pragma unroll
    for (int ks=0; ks<8; ks++){
        int k0 = ks*16;
        uint32_t a[2][4], b[2];
        lda(a[0], hb, wm*32,    k0, lane);
        lda(a[1], hb, wm*32+16, k0, lane);
        #pragma unroll
        for (int ni=0; ni<8; ni++){
            ldb_kn(b, wb2, wn*64+ni*8, k0, lane);
            mma16816(acc2[0][ni], a[0], b);
            mma16816(acc2[1][ni], a[1], b);
        }
    }
    __syncthreads();

    float* F = (float*)dyn;
    #pragma unroll
    for (int mi=0; mi<2; mi++)
        #pragma unroll
        for (int ni=0; ni<8; ni++){
            int r0 = wm*32 + mi*16 + fr;
            int c  = wn*64 + ni*8 + fc;
            F[r0*PITCHF + c]         = acc2[mi][ni][0] + b2g[c];
            F[r0*PITCHF + c + 1]     = acc2[mi][ni][1] + b2g[c+1];
            F[(r0+8)*PITCHF + c]     = acc2[mi][ni][2] + b2g[c];
            F[(r0+8)*PITCHF + c + 1] = acc2[mi][ni][3] + b2g[c+1];
        }
    __syncthreads();

    float scale = which ? 1.44269504088896341f * expf(-lt[0]) : 1.0f;
    #pragma unroll 1
    for (int rr=0; rr<16; rr++){
        int r = warp*16 + rr;
        float4 v = *(const float4*)(F + r*PITCHF + lane*4);
        float s = v.x*v.x + v.y*v.y + v.z*v.z + v.w*v.w;
        #pragma unroll
        for (int o=16; o; o>>=1) s += __shfl_xor_sync(0xffffffffu, s, o);
        float inv = scale / fmaxf(sqrtf(s), 1e-12f);
        float e0 = v.x*inv, e1 = v.y*inv, e2 = v.z*inv, e3 = v.w*inv;
        __nv_bfloat162* dst = (__nv_bfloat162*)(E + (size_t)(rowbase+r)*PD + lane*4);
        dst[0] = __floats2bfloat162_rn(e0, e1);
        dst[1] = __floats2bfloat162_rn(e2, e3);
        *(uint32_t*)(E8 + (size_t)(rowbase+r)*PD + lane*4) = pack_e4m3(e0, e1, e2, e3);
    }
}

// ---------------- fp8 logits kernel (B-resident, register col-sums) ----------------
// 296 CTAs; CTA bid owns tiles t in [bid*16384/296, (bid+1)*16384/296), column-major
// order t = colb*128 + rowa. B tile fixed per column block (staged <=2x per CTA);
// A double-buffered cp.async; csum accumulates in registers, flushed per column block.
__global__ __launch_bounds__(256, 2)
void logits_fp8()
{
    extern __shared__ uint8_t dyn8[];
    const uint32_t base = smem_u32(dyn8);
    const uint32_t sBf = base + 2*TILEB;
    const int tid = threadIdx.x, lane = tid & 31, warp = tid >> 5;
    const int wm = warp & 3, wn = warp >> 2;
    const int bid = blockIdx.x;

    const int t0 = (int)(((long long)bid     * 16384) / 296);
    const int t1 = (int)(((long long)(bid+1) * 16384) / 296);

    auto stageA = [&](int rowa, int b){
        const uint8_t* gA = g_ip8 + (size_t)(rowa*128) * PD;
        const uint32_t d = base + b*TILEB;
        #pragma unroll
        for (int it=0; it<4; it++){
            int seg = it*256 + tid;
            int r = seg >> 3, c = (seg & 7)*16;
            CP16(d + (uint32_t)(r*PB + c), gA + r*PD + c);
        }
    };
    auto loadB = [&](int colb){
        __syncthreads();
        const uint8_t* gB = g_np8 + (size_t)(colb*128) * PD;
        #pragma unroll
        for (int it=0; it<4; it++){
            int seg = it*256 + tid;
            int r = seg >> 3, c = (seg & 7)*16;
            uint4 v = *(const uint4*)(gB + r*PD + c);
            asm volatile("st.shared.v4.b32 [%0],{%1,%2,%3,%4};"
                :: "r"(sBf + (uint32_t)(r*PB + c)), "r"(v.x),"r"(v.y),"r"(v.z),"r"(v.w));
        }
        __syncthreads();
    };

    float csum[8][2];
    #pragma unroll
    for (int i=0;i<8;i++) csum[i][0] = csum[i][1] = 0.f;

    auto flushC = [&](int colb){
        #pragma unroll
        for (int ni=0; ni<8; ni++)
            #pragma unroll
            for (int jj=0; jj<2; jj++){
                float v = csum[ni][jj];
                v += __shfl_xor_sync(0xffffffffu, v, 4);
                v += __shfl_xor_sync(0xffffffffu, v, 8);
                v += __shfl_xor_sync(0xffffffffu, v, 16);
                if (lane < 4)
                    atomicAdd(&g_colsum[colb*128 + wn*64 + ni*8 + 2*lane + jj], v);
                csum[ni][jj] = 0.f;
            }
    };

    int colb_cur = t0 >> 7;
    loadB(colb_cur);
    stageA(t0 & 127, 0); CP_COMMIT();

    for (int t = t0; t < t1; t++){
        const int rowa = t & 127, colb = t >> 7;
        if (colb != colb_cur){
            flushC(colb_cur);
            colb_cur = colb;
            loadB(colb);
        }
        int buf = (t - t0) & 1;
        if (t+1 < t1){ stageA((t+1) & 127, buf^1); CP_COMMIT(); CP_WAIT1(); }
        else         { CP_WAIT0(); }
        __syncthreads();

        const uint32_t sA = base + buf*TILEB;

        float acc[2][8][4];
        #pragma unroll
        for (int i=0;i<2;i++)
            #pragma unroll
            for (int j=0;j<8;j++)
                #pragma unroll
                for (int k=0;k<4;k++) acc[i][j][k] = 0.f;

        #pragma unroll
        for (int ks=0; ks<4; ks++){
            int k0b = ks*32;
            uint32_t a[2][4], b[2];
            lda8(a[0], sA, wm*32,    k0b, lane);
            lda8(a[1], sA, wm*32+16, k0b, lane);
            #pragma unroll
            for (int ni=0; ni<8; ni++){
                ldb8(b, sBf, wn*64+ni*8, k0b, lane);
                mma_fp8(acc[0][ni], a[0], b);
                mma_fp8(acc[1][ni], a[1], b);
            }
        }

        // exp2 + row sums (atomics) + col sums (registers)
        float rsum[2][2];
        #pragma unroll
        for (int i=0;i<2;i++) rsum[i][0] = rsum[i][1] = 0.f;

        #pragma unroll
        for (int mi=0; mi<2; mi++)
            #pragma unroll
            for (int ni=0; ni<8; ni++){
                float p0 = ex2f(acc[mi][ni][0]);
                float p1 = ex2f(acc[mi][ni][1]);
                float p2 = ex2f(acc[mi][ni][2]);
                float p3 = ex2f(acc[mi][ni][3]);
                rsum[mi][0] += p0 + p1;
                rsum[mi][1] += p2 + p3;
                csum[ni][0] += p0 + p2;
                csum[ni][1] += p1 + p3;
            }

        #pragma unroll
        for (int mi=0; mi<2; mi++)
            #pragma unroll
            for (int rr=0; rr<2; rr++){
                float v = rsum[mi][rr];
                v += __shfl_xor_sync(0xffffffffu, v, 1);
                v += __shfl_xor_sync(0xffffffffu, v, 2);
                if ((lane & 3) == 0)
                    atomicAdd(&g_rowsum[rowa*128 + wm*32 + mi*16 + rr*8 + (lane>>2)], v);
            }

        __syncthreads();
    }
    flushC(colb_cur);
}

// ---------------- loss assembly ----------------
__global__ void loss_part()
{
    __shared__ float red[256];
    int row = blockIdx.x*256 + threadIdx.x;
    const uint4* pi = (const uint4*)(g_ip + (size_t)row*PD);
    const uint4* pn = (const uint4*)(g_np + (size_t)row*PD);
    float dot = 0.f;
    #pragma unroll
    for (int i=0; i<16; i++){
        uint4 a = pi[i], b = pn[i];
        const __nv_bfloat162* pa = (const __nv_bfloat162*)&a;
        const __nv_bfloat162* pb = (const __nv_bfloat162*)&b;
        #pragma unroll
        for (int j=0; j<4; j++){
            float2 fa = __bfloat1622float2(pa[j]);
            float2 fb = __bfloat1622float2(pb[j]);
            dot += fa.x*fb.x + fa.y*fb.y;
        }
    }
    float val = 0.5f*(logf(g_rowsum[row]) + logf(g_colsum[row]))
              - dot * 0.69314718055994531f;
    red[threadIdx.x] = val;
    __syncthreads();
    #pragma unroll
    for (int o=128; o; o>>=1){
        if (threadIdx.x < o) red[threadIdx.x] += red[threadIdx.x + o];
        __syncthreads();
    }
    if (threadIdx.x == 0) g_part[blockIdx.x] = red[0];
}

__global__ void loss_final(float* out)
{
    int l = threadIdx.x;
    float v = g_part[l] + g_part[l+32];
    #pragma unroll
    for (int o=16; o; o>>=1) v += __shfl_xor_sync(0xffffffffu, v, o);
    if (l == 0) out[0] = v * (1.0f/16384.0f);
}

// ---------------- launcher ----------------
extern "C" void kernel_launch(void* const* d_in, const int* in_sizes, int n_in,
                              void* d_out, int out_size)
{
    (void)in_sizes; (void)n_in; (void)out_size;
    const float* img = (const float*)d_in[0];
    const float* num = (const float*)d_in[1];
    const float* Wi1 = (const float*)d_in[2];
    const float* bi1 = (const float*)d_in[3];
    const float* Wi2 = (const float*)d_in[4];
    const float* bi2 = (const float*)d_in[5];
    const float* Wn1 = (const float*)d_in[6];
    const float* bn1 = (const float*)d_in[7];
    const float* Wn2 = (const float*)d_in[8];
    const float* bn2 = (const float*)d_in[9];
    const float* lt  = (const float*)d_in[10];
    float* out = (float*)d_out;

    cudaFuncSetAttribute(mlp_all,    cudaFuncAttributeMaxDynamicSharedMemorySize, MLP_SMEM);
    cudaFuncSetAttribute(logits_fp8, cudaFuncAttributeMaxDynamicSharedMemorySize, LOG_SMEM);

    convert_small<<<128, 256>>>(Wi2, Wn1, Wn2);                          // 1
    convert_big<<<1024, 256>>>(Wi1);                                     // 2
    mlp_all<<<256, 256, MLP_SMEM>>>(img, num, bi1, bi2, bn1, bn2, lt);   // 3
    logits_fp8<<<296, 256, LOG_SMEM>>>();                                // 4
    loss_part<<<64, 256>>>();                                            // 5
    loss_final<<<1, 32>>>(out);                                          // 6
}